// round 15
// baseline (speedup 1.0000x reference)
#include <cuda_runtime.h>
#include <cuda_fp16.h>
#include <cstdint>

#define NBATCH   8
#define NC       2048
#define NF       8192
#define MTOT     (NBATCH * NF)   // 65536
#define CC       256
#define CS       128
#define CIN      384
#define H1W      512
#define H2W      256
#define GN_EPS   1e-5f

// ---------------- scratch (allocation-free rule) ----------------
__device__ __half g_a1[(size_t)MTOT * CIN];    // 48 MB, single fp16
__device__ __half g_h1[(size_t)MTOT * H1W];    // 64 MB, single fp16
__device__ __half g_w1h[H1W * CIN], g_w1l[H1W * CIN];
__device__ __half g_w2h[H2W * H1W], g_w2l[H2W * H1W];
__device__ float4 g_knn_w[MTOT];               // normalized weights (w0,w1,w2,-)
__device__ int4   g_knn_i[MTOT];               // global coarse row ids (r0,r1,r2,-)

// ---------------- PTX helpers (base ISA only) ----------------
__device__ __forceinline__ uint32_t smem_u32(const void* p) {
    uint32_t a;
    asm("{ .reg .u64 t; cvta.to.shared.u64 t, %1; cvt.u32.u64 %0, t; }" : "=r"(a) : "l"(p));
    return a;
}
__device__ __forceinline__ void cp16(uint32_t dst, const void* src) {
    asm volatile("cp.async.cg.shared.global [%0], [%1], 16;" :: "r"(dst), "l"(src));
}
#define CP_COMMIT() asm volatile("cp.async.commit_group;" ::: "memory")
#define CP_WAIT(n)  asm volatile("cp.async.wait_group %0;" :: "n"(n) : "memory")

__device__ __forceinline__ void ldsm4(uint32_t* r, uint32_t addr) {
    asm volatile("ldmatrix.sync.aligned.m8n8.x4.shared.b16 {%0,%1,%2,%3}, [%4];"
                 : "=r"(r[0]), "=r"(r[1]), "=r"(r[2]), "=r"(r[3]) : "r"(addr));
}
__device__ __forceinline__ void mma16816(float* d, const uint32_t* a, const uint32_t* b) {
    asm volatile("mma.sync.aligned.m16n8k16.row.col.f32.f16.f16.f32 "
                 "{%0,%1,%2,%3}, {%4,%5,%6,%7}, {%8,%9}, {%0,%1,%2,%3};"
                 : "+f"(d[0]), "+f"(d[1]), "+f"(d[2]), "+f"(d[3])
                 : "r"(a[0]), "r"(a[1]), "r"(a[2]), "r"(a[3]), "r"(b[0]), "r"(b[1]));
}
__device__ __forceinline__ uint32_t swz(uint32_t b) { return b ^ ((b >> 3) & 0x70); }
__device__ __forceinline__ uint32_t pack_h2(__half a, __half b) {
    return (uint32_t)__half_as_ushort(a) | ((uint32_t)__half_as_ushort(b) << 16);
}
__device__ __forceinline__ void split_h(float v, __half& h, __half& l) {
    h = __float2half_rn(v);
    l = __float2half_rn(v - __half2float(h));
}

// ---------------------------------------------------------------------------
// Split BOTH weight matrices in one launch.
// ---------------------------------------------------------------------------
__global__ __launch_bounds__(256) void split_kernel(
    const float* __restrict__ w1, __half* __restrict__ h1, __half* __restrict__ l1, int n1,
    const float* __restrict__ w2, __half* __restrict__ h2, __half* __restrict__ l2, int n2)
{
    int i = blockIdx.x * 256 + threadIdx.x;
    if (i < n1) {
        __half hh, ll; split_h(w1[i], hh, ll); h1[i] = hh; l1[i] = ll;
    } else if (i < n1 + n2) {
        int j = i - n1;
        __half hh, ll; split_h(w2[j], hh, ll); h2[j] = hh; l2[j] = ll;
    }
}

// ---------------------------------------------------------------------------
// kNN scan: 512-thr blocks, 8 lanes/point, 64 points/block. Identical distance
// and merge math to the passing kernels; writes per-point (rows, weights)
// records instead of gathering. Tail passthroughs folded in.
// ---------------------------------------------------------------------------
__global__ __launch_bounds__(512) void knn_scan_kernel(
    const float* __restrict__ pos, const float* __restrict__ pos_skip,
    const float* __restrict__ refl_skip, float* __restrict__ out)
{
    __shared__ float4 spos[NC];   // interleaved: spos[8*jj + q] = posb[q*256 + jj]
    const int tid   = threadIdx.x;
    const int b     = blockIdx.x >> 7;
    const int chunk = blockIdx.x & 127;

    const float* posb = pos + (size_t)b * NC * 3;
    for (int i = tid; i < NC; i += 512) {
        int q = i >> 8, jj = i & 255;
        spos[8 * jj + q] = make_float4(posb[i * 3], posb[i * 3 + 1], posb[i * 3 + 2], 0.f);
    }
    __syncthreads();

    const int pt = tid >> 3;
    const int q  = tid & 7;
    const int f = b * NF + chunk * 64 + pt;
    const float px = pos_skip[(size_t)f * 3 + 0];
    const float py = pos_skip[(size_t)f * 3 + 1];
    const float pz = pos_skip[(size_t)f * 3 + 2];

    {   // folded tail passthroughs
        float* out_pos   = out + (size_t)MTOT * H2W;
        float* out_refl  = out_pos + (size_t)MTOT * 3;
        float* out_batch = out_refl + MTOT;
        if (q == 0) {
            out_pos[(size_t)f * 3 + 0] = px;
            out_pos[(size_t)f * 3 + 1] = py;
            out_pos[(size_t)f * 3 + 2] = pz;
        } else if (q == 1) {
            out_refl[f] = refl_skip[f];
        } else if (q == 2) {
            out_batch[f] = (float)(f >> 13);
        }
    }

    float bd0 = 3.4e38f, bd1 = 3.4e38f, bd2 = 3.4e38f;
    int   bi0 = 0, bi1 = 0, bi2 = 0;
    const int joff = q << 8;

    #pragma unroll 4
    for (int jj = 0; jj < 256; jj++) {
        float4 c = spos[8 * jj + q];
        float dx = px - c.x, dy = py - c.y, dz = pz - c.z;
        float d2 = fmaf(dx, dx, fmaf(dy, dy, dz * dz));
        int j = joff + jj;
        if (d2 < bd2) {
            if (d2 < bd1) {
                if (d2 < bd0) { bd2 = bd1; bi2 = bi1; bd1 = bd0; bi1 = bi0; bd0 = d2; bi0 = j; }
                else          { bd2 = bd1; bi2 = bi1; bd1 = d2;  bi1 = j; }
            } else            { bd2 = d2;  bi2 = j; }
        }
    }

    const unsigned FULL = 0xffffffffu;
    #pragma unroll
    for (int lvl = 0; lvl < 3; lvl++) {
        const int delta = 1 << lvl;
        const bool amLow = ((q & delta) == 0);
        float od0 = __shfl_xor_sync(FULL, bd0, delta);
        float od1 = __shfl_xor_sync(FULL, bd1, delta);
        float od2 = __shfl_xor_sync(FULL, bd2, delta);
        int   oi0 = __shfl_xor_sync(FULL, bi0, delta);
        int   oi1 = __shfl_xor_sync(FULL, bi1, delta);
        int   oi2 = __shfl_xor_sync(FULL, bi2, delta);

        float ld0 = amLow ? bd0 : od0, ld1 = amLow ? bd1 : od1, ld2 = amLow ? bd2 : od2;
        int   li0 = amLow ? bi0 : oi0, li1 = amLow ? bi1 : oi1, li2 = amLow ? bi2 : oi2;
        float hd0 = amLow ? od0 : bd0, hd1 = amLow ? od1 : bd1, hd2 = amLow ? od2 : bd2;
        int   hi0 = amLow ? oi0 : bi0, hi1 = amLow ? oi1 : bi1, hi2 = amLow ? oi2 : bi2;

        bool tA = ld0 <= hd0;
        float m0 = tA ? ld0 : hd0;  int x0 = tA ? li0 : hi0;
        float c1a = tA ? ld1 : ld0; int i1a = tA ? li1 : li0;
        float c1b = tA ? hd0 : hd1; int i1b = tA ? hi0 : hi1;
        bool tB = c1a <= c1b;
        float m1 = tB ? c1a : c1b;  int x1 = tB ? i1a : i1b;
        float c2a = tB ? (tA ? ld2 : ld1) : c1a;  int i2a = tB ? (tA ? li2 : li1) : i1a;
        float c2b = tB ? c1b : (tA ? hd1 : hd2);  int i2b = tB ? i1b : (tA ? hi1 : hi2);
        bool tC = c2a <= c2b;
        float m2 = tC ? c2a : c2b;  int x2 = tC ? i2a : i2b;

        bd0 = m0; bi0 = x0; bd1 = m1; bi1 = x1; bd2 = m2; bi2 = x2;
    }

    if (q == 0) {
        float w0 = 1.f / fmaxf(bd0, 1e-16f);
        float w1 = 1.f / fmaxf(bd1, 1e-16f);
        float w2 = 1.f / fmaxf(bd2, 1e-16f);
        const float inv = 1.f / (w0 + w1 + w2);
        g_knn_w[f] = make_float4(w0 * inv, w1 * inv, w2 * inv, 0.f);
        g_knn_i[f] = make_int4(b * NC + bi0, b * NC + bi1, b * NC + bi2, 0);
    }
}

// ---------------------------------------------------------------------------
// Gather: no smem, 256-thr blocks (near-full occupancy) — hides L2 latency.
// 8 lanes per point, 32 points per block.
// ---------------------------------------------------------------------------
__global__ __launch_bounds__(256) void gather_kernel(
    const float* __restrict__ x, const float* __restrict__ x_skip)
{
    const int tid = threadIdx.x;
    const int pt  = tid >> 3;    // 0..31
    const int q   = tid & 7;
    const int f   = blockIdx.x * 32 + pt;

    const float4 w = g_knn_w[f];
    const int4   n = g_knn_i[f];

    const float4* r0 = (const float4*)(x + (size_t)n.x * CC);
    const float4* r1 = (const float4*)(x + (size_t)n.y * CC);
    const float4* r2 = (const float4*)(x + (size_t)n.z * CC);
    const float4* xs = (const float4*)(x_skip + (size_t)f * CS);
    uint4* ga = (uint4*)(g_a1 + (size_t)f * CIN);

    // 48 uint4 blocks of 8 channels: [0,32) interp, [32,48) skip. Split 8 ways.
    #pragma unroll
    for (int c8 = q; c8 < CIN / 8; c8 += 8) {
        float o[8];
        if (c8 < CC / 8) {
            float4 a0 = r0[2 * c8], a1 = r0[2 * c8 + 1];
            float4 b0 = r1[2 * c8], b1 = r1[2 * c8 + 1];
            float4 e0 = r2[2 * c8], e1 = r2[2 * c8 + 1];
            o[0] = w.x*a0.x + w.y*b0.x + w.z*e0.x;  o[1] = w.x*a0.y + w.y*b0.y + w.z*e0.y;
            o[2] = w.x*a0.z + w.y*b0.z + w.z*e0.z;  o[3] = w.x*a0.w + w.y*b0.w + w.z*e0.w;
            o[4] = w.x*a1.x + w.y*b1.x + w.z*e1.x;  o[5] = w.x*a1.y + w.y*b1.y + w.z*e1.y;
            o[6] = w.x*a1.z + w.y*b1.z + w.z*e1.z;  o[7] = w.x*a1.w + w.y*b1.w + w.z*e1.w;
        } else {
            int s8 = c8 - CC / 8;
            float4 s0 = xs[2 * s8], s1 = xs[2 * s8 + 1];
            o[0] = s0.x; o[1] = s0.y; o[2] = s0.z; o[3] = s0.w;
            o[4] = s1.x; o[5] = s1.y; o[6] = s1.z; o[7] = s1.w;
        }
        uint32_t hw[4];
        #pragma unroll
        for (int k = 0; k < 4; k++)
            hw[k] = pack_h2(__float2half_rn(o[2*k]), __float2half_rn(o[2*k+1]));
        ga[c8] = make_uint4(hw[0], hw[1], hw[2], hw[3]);
    }
}

// ---------------------------------------------------------------------------
// mma.sync fp16 GEMM, 2 MMA terms — round-11 best config: CTA tile 128x128,
// 256 threads, K-stage 64 double-buffered (96 KB/CTA), 2 CTAs/SM.
// ---------------------------------------------------------------------------
#define TILEB    16384                 // 128 rows x 128B (64 fp16)
#define STAGEB   (3 * TILEB)           // A, Bh, Bl = 48 KB
#define GEMM_SMEM (2 * STAGEB)         // 96 KB

__global__ __launch_bounds__(256, 2) void gemm_mma_kernel(
    const __half* __restrict__ A,
    const __half* __restrict__ Bh, const __half* __restrict__ Bl,
    const float* __restrict__ bias, int K, int mode,
    __half* __restrict__ outA, float* __restrict__ outF,
    const float* __restrict__ gamma, const float* __restrict__ beta, int Nld)
{
    extern __shared__ char smem[];
    const uint32_t sbase = smem_u32(smem);
    const int tid = threadIdx.x;
    const int wid = tid >> 5, lid = tid & 31;
    const int warp_m = wid >> 2, warp_n = wid & 3;
    const int bm = blockIdx.y * 128, bn = blockIdx.x * 128;

    const int lr = tid >> 3;   // 0..31
    const int lu = tid & 7;    // 16B unit in 128B row
    const __half* gsrc[3] = {
        A  + (size_t)(bm + lr) * K + lu * 8,
        Bh + (size_t)(bn + lr) * K + lu * 8,
        Bl + (size_t)(bn + lr) * K + lu * 8 };

    const int nStages = K >> 6;

    auto load_stage = [&](int s) {
        const uint32_t dbase = sbase + (uint32_t)(s & 1) * STAGEB;
        const int k0 = s << 6;
        #pragma unroll
        for (int mtx = 0; mtx < 3; mtx++) {
            #pragma unroll
            for (int i = 0; i < 4; i++) {
                uint32_t byte = (uint32_t)(lr + i * 32) * 128 + lu * 16;
                cp16(dbase + mtx * TILEB + swz(byte),
                     gsrc[mtx] + (size_t)(i * 32) * K + k0);
            }
        }
        CP_COMMIT();
    };

    float acc[4][4][4];
    #pragma unroll
    for (int a = 0; a < 4; a++)
        #pragma unroll
        for (int b = 0; b < 4; b++)
            #pragma unroll
            for (int c = 0; c < 4; c++) acc[a][b][c] = 0.f;

    const int g  = lid >> 3;
    const int gr = lid & 7;
    const uint32_t aRow = warp_m * 64 + (g & 1) * 8 + gr;
    const uint32_t aCol = (uint32_t)(g >> 1) * 16;
    const uint32_t bRow = warp_n * 32 + (g >> 1) * 8 + gr;
    const uint32_t bCol = (uint32_t)(g & 1) * 16;

    load_stage(0);

    for (int s = 0; s < nStages; s++) {
        if (s + 1 < nStages) { load_stage(s + 1); CP_WAIT(1); }
        else                 { CP_WAIT(0); }
        __syncthreads();

        const uint32_t tb = sbase + (uint32_t)(s & 1) * STAGEB;
        #pragma unroll
        for (int kstep = 0; kstep < 4; kstep++) {
            const uint32_t kb = (uint32_t)kstep * 32;
            uint32_t ah[4][4], bh[4][2], bl[4][2];
            #pragma unroll
            for (int mf = 0; mf < 4; mf++) {
                uint32_t byte = (aRow + mf * 16) * 128 + aCol + kb;
                ldsm4(ah[mf], tb + swz(byte));
            }
            #pragma unroll
            for (int p = 0; p < 2; p++) {
                uint32_t byte = (bRow + p * 16) * 128 + bCol + kb;
                uint32_t rh[4], rl[4];
                ldsm4(rh, tb + TILEB + swz(byte));
                ldsm4(rl, tb + 2 * TILEB + swz(byte));
                bh[2*p][0] = rh[0]; bh[2*p][1] = rh[1];
                bh[2*p+1][0] = rh[2]; bh[2*p+1][1] = rh[3];
                bl[2*p][0] = rl[0]; bl[2*p][1] = rl[1];
                bl[2*p+1][0] = rl[2]; bl[2*p+1][1] = rl[3];
            }
            #pragma unroll
            for (int mf = 0; mf < 4; mf++)
                #pragma unroll
                for (int nf = 0; nf < 4; nf++) {
                    mma16816(acc[mf][nf], ah[mf], bh[nf]);
                    mma16816(acc[mf][nf], ah[mf], bl[nf]);
                }
        }
        __syncthreads();
    }

    // ---------------- epilogue ----------------
    #pragma unroll
    for (int mf = 0; mf < 4; mf++) {
        const int r0 = bm + warp_m * 64 + mf * 16 + (lid >> 2);
        const int r1 = r0 + 8;
        #pragma unroll
        for (int nf = 0; nf < 4; nf++) {
            const int c0 = bn + warp_n * 32 + nf * 8 + 2 * (lid & 3);
            const float bi0 = __ldg(bias + c0), bi1 = __ldg(bias + c0 + 1);
            float v00 = fmaxf(acc[mf][nf][0] + bi0, 0.f);
            float v01 = fmaxf(acc[mf][nf][1] + bi1, 0.f);
            float v10 = fmaxf(acc[mf][nf][2] + bi0, 0.f);
            float v11 = fmaxf(acc[mf][nf][3] + bi1, 0.f);

            if (mode == 0) {
                *(uint32_t*)(outA + (size_t)r0 * Nld + c0) =
                    pack_h2(__float2half_rn(v00), __float2half_rn(v01));
                *(uint32_t*)(outA + (size_t)r1 * Nld + c0) =
                    pack_h2(__float2half_rn(v10), __float2half_rn(v11));
            } else {
                float s1a = v00 + v01, s2a = v00 * v00 + v01 * v01;
                float s1b = v10 + v11, s2b = v10 * v10 + v11 * v11;
                s1a += __shfl_xor_sync(0xffffffffu, s1a, 1);
                s2a += __shfl_xor_sync(0xffffffffu, s2a, 1);
                s1b += __shfl_xor_sync(0xffffffffu, s1b, 1);
                s2b += __shfl_xor_sync(0xffffffffu, s2b, 1);
                s1a += __shfl_xor_sync(0xffffffffu, s1a, 2);
                s2a += __shfl_xor_sync(0xffffffffu, s2a, 2);
                s1b += __shfl_xor_sync(0xffffffffu, s1b, 2);
                s2b += __shfl_xor_sync(0xffffffffu, s2b, 2);
                const float mua = s1a * 0.125f, mub = s1b * 0.125f;
                const float isa = rsqrtf(s2a * 0.125f - mua * mua + GN_EPS);
                const float isb = rsqrtf(s2b * 0.125f - mub * mub + GN_EPS);
                const float g0 = __ldg(gamma + c0), g1 = __ldg(gamma + c0 + 1);
                const float t0 = __ldg(beta + c0),  t1 = __ldg(beta + c0 + 1);
                float2 oa = make_float2((v00 - mua) * isa * g0 + t0,
                                        (v01 - mua) * isa * g1 + t1);
                float2 ob = make_float2((v10 - mub) * isb * g0 + t0,
                                        (v11 - mub) * isb * g1 + t1);
                *(float2*)(outF + (size_t)r0 * Nld + c0) = oa;
                *(float2*)(outF + (size_t)r1 * Nld + c0) = ob;
            }
        }
    }
}

// ---------------------------------------------------------------------------
extern "C" void kernel_launch(void* const* d_in, const int* in_sizes, int n_in,
                              void* d_out, int out_size)
{
    const float* x         = (const float*)d_in[0];
    const float* pos       = (const float*)d_in[1];
    const float* x_skip    = (const float*)d_in[4];
    const float* pos_skip  = (const float*)d_in[5];
    const float* refl_skip = (const float*)d_in[6];
    const float* W1 = (const float*)d_in[8];
    const float* b1 = (const float*)d_in[9];
    const float* W2 = (const float*)d_in[10];
    const float* b2 = (const float*)d_in[11];
    const float* gamma = (const float*)d_in[12];
    const float* beta  = (const float*)d_in[13];
    float* out = (float*)d_out;

    __half *a1p, *h1p, *w1h, *w1l, *w2h, *w2l;
    cudaGetSymbolAddress((void**)&a1p, g_a1);
    cudaGetSymbolAddress((void**)&h1p, g_h1);
    cudaGetSymbolAddress((void**)&w1h, g_w1h);
    cudaGetSymbolAddress((void**)&w1l, g_w1l);
    cudaGetSymbolAddress((void**)&w2h, g_w2h);
    cudaGetSymbolAddress((void**)&w2l, g_w2l);

    static bool attr_done = false;
    if (!attr_done) {
        cudaFuncSetAttribute(gemm_mma_kernel,
                             cudaFuncAttributeMaxDynamicSharedMemorySize, GEMM_SMEM);
        attr_done = true;
    }

    const int n1 = H1W * CIN, n2 = H2W * H1W;
    split_kernel<<<(n1 + n2 + 255) / 256, 256>>>(W1, w1h, w1l, n1, W2, w2h, w2l, n2);

    // kNN scan (+ tail passthroughs), then high-occupancy gather
    knn_scan_kernel<<<NBATCH * 128, 512>>>(pos, pos_skip, refl_skip, out);
    gather_kernel<<<MTOT / 32, 256>>>(x, x_skip);

    // layer 1: h1 = relu(a1 @ W1^T + b1) -> fp16   [65536, 512]
    {
        dim3 grid(H1W / 128, MTOT / 128);
        gemm_mma_kernel<<<grid, 256, GEMM_SMEM>>>(
            a1p, w1h, w1l, b1, CIN, 0, h1p, nullptr, nullptr, nullptr, H1W);
    }
    // layer 2: out = GN(relu(h1 @ W2^T + b2))      [65536, 256]
    {
        dim3 grid(H2W / 128, MTOT / 128);
        gemm_mma_kernel<<<grid, 256, GEMM_SMEM>>>(
            h1p, w2h, w2l, b2, H1W, 1, nullptr, out, gamma, beta, H2W);
    }
}

// round 16
// speedup vs baseline: 1.0584x; 1.0584x over previous
#include <cuda_runtime.h>
#include <cuda_fp16.h>
#include <cstdint>

#define NBATCH   8
#define NC       2048
#define NF       8192
#define MTOT     (NBATCH * NF)   // 65536
#define CC       256
#define CS       128
#define CIN      384
#define H1W      512
#define H2W      256
#define GN_EPS   1e-5f

// ---------------- scratch (allocation-free rule) ----------------
__device__ __half g_a1[(size_t)MTOT * CIN];    // 48 MB, single fp16
__device__ __half g_h1[(size_t)MTOT * H1W];    // 64 MB, single fp16
__device__ __half g_w1h[H1W * CIN], g_w1l[H1W * CIN];
__device__ __half g_w2h[H2W * H1W], g_w2l[H2W * H1W];

// ---------------- PTX helpers (base ISA only) ----------------
__device__ __forceinline__ uint32_t smem_u32(const void* p) {
    uint32_t a;
    asm("{ .reg .u64 t; cvta.to.shared.u64 t, %1; cvt.u32.u64 %0, t; }" : "=r"(a) : "l"(p));
    return a;
}
__device__ __forceinline__ void cp16(uint32_t dst, const void* src) {
    asm volatile("cp.async.cg.shared.global [%0], [%1], 16;" :: "r"(dst), "l"(src));
}
#define CP_COMMIT() asm volatile("cp.async.commit_group;" ::: "memory")
#define CP_WAIT(n)  asm volatile("cp.async.wait_group %0;" :: "n"(n) : "memory")

__device__ __forceinline__ void ldsm4(uint32_t* r, uint32_t addr) {
    asm volatile("ldmatrix.sync.aligned.m8n8.x4.shared.b16 {%0,%1,%2,%3}, [%4];"
                 : "=r"(r[0]), "=r"(r[1]), "=r"(r[2]), "=r"(r[3]) : "r"(addr));
}
__device__ __forceinline__ void mma16816(float* d, const uint32_t* a, const uint32_t* b) {
    asm volatile("mma.sync.aligned.m16n8k16.row.col.f32.f16.f16.f32 "
                 "{%0,%1,%2,%3}, {%4,%5,%6,%7}, {%8,%9}, {%0,%1,%2,%3};"
                 : "+f"(d[0]), "+f"(d[1]), "+f"(d[2]), "+f"(d[3])
                 : "r"(a[0]), "r"(a[1]), "r"(a[2]), "r"(a[3]), "r"(b[0]), "r"(b[1]));
}
__device__ __forceinline__ uint32_t swz(uint32_t b) { return b ^ ((b >> 3) & 0x70); }
__device__ __forceinline__ uint32_t pack_h2(__half a, __half b) {
    return (uint32_t)__half_as_ushort(a) | ((uint32_t)__half_as_ushort(b) << 16);
}
__device__ __forceinline__ void split_h(float v, __half& h, __half& l) {
    h = __float2half_rn(v);
    l = __float2half_rn(v - __half2float(h));
}

// ---------------------------------------------------------------------------
// Split BOTH weight matrices in one launch.
// ---------------------------------------------------------------------------
__global__ __launch_bounds__(256) void split_kernel(
    const float* __restrict__ w1, __half* __restrict__ h1, __half* __restrict__ l1, int n1,
    const float* __restrict__ w2, __half* __restrict__ h2, __half* __restrict__ l2, int n2)
{
    int i = blockIdx.x * 256 + threadIdx.x;
    if (i < n1) {
        __half hh, ll; split_h(w1[i], hh, ll); h1[i] = hh; l1[i] = ll;
    } else if (i < n1 + n2) {
        int j = i - n1;
        __half hh, ll; split_h(w2[j], hh, ll); h2[j] = hh; l2[j] = ll;
    }
}

// ---------------------------------------------------------------------------
// kNN(k=3): round-11 best structure — 4 lanes/point, 256-thr blocks, 64
// points/block. Tail passthroughs folded into lanes q=0/1/2.
// ---------------------------------------------------------------------------
__global__ __launch_bounds__(256) void knn_interp_kernel(
    const float* __restrict__ x, const float* __restrict__ pos,
    const float* __restrict__ pos_skip, const float* __restrict__ x_skip,
    const float* __restrict__ refl_skip, float* __restrict__ out)
{
    __shared__ float4 spos[NC];   // interleaved: spos[4*jj + q] = posb[q*512 + jj]
    const int tid   = threadIdx.x;
    const int b     = blockIdx.x >> 7;
    const int chunk = blockIdx.x & 127;

    const float* posb = pos + (size_t)b * NC * 3;
    for (int i = tid; i < NC; i += 256) {
        int q = i >> 9, jj = i & 511;
        spos[4 * jj + q] = make_float4(posb[i * 3], posb[i * 3 + 1], posb[i * 3 + 2], 0.f);
    }
    __syncthreads();

    const int pt = tid >> 2;
    const int q  = tid & 3;
    const int f = b * NF + chunk * 64 + pt;
    const float px = pos_skip[(size_t)f * 3 + 0];
    const float py = pos_skip[(size_t)f * 3 + 1];
    const float pz = pos_skip[(size_t)f * 3 + 2];

    {   // folded tail passthroughs (one lane each)
        float* out_pos   = out + (size_t)MTOT * H2W;
        float* out_refl  = out_pos + (size_t)MTOT * 3;
        float* out_batch = out_refl + MTOT;
        if (q == 0) {
            out_pos[(size_t)f * 3 + 0] = px;
            out_pos[(size_t)f * 3 + 1] = py;
            out_pos[(size_t)f * 3 + 2] = pz;
        } else if (q == 1) {
            out_refl[f] = refl_skip[f];
        } else if (q == 2) {
            out_batch[f] = (float)(f >> 13);
        }
    }

    float bd0 = 3.4e38f, bd1 = 3.4e38f, bd2 = 3.4e38f;
    int   bi0 = 0, bi1 = 0, bi2 = 0;
    const int joff = q << 9;

    #pragma unroll 4
    for (int jj = 0; jj < 512; jj++) {
        float4 c = spos[4 * jj + q];
        float dx = px - c.x, dy = py - c.y, dz = pz - c.z;
        float d2 = fmaf(dx, dx, fmaf(dy, dy, dz * dz));
        int j = joff + jj;
        if (d2 < bd2) {
            if (d2 < bd1) {
                if (d2 < bd0) { bd2 = bd1; bi2 = bi1; bd1 = bd0; bi1 = bi0; bd0 = d2; bi0 = j; }
                else          { bd2 = bd1; bi2 = bi1; bd1 = d2;  bi1 = j; }
            } else            { bd2 = d2;  bi2 = j; }
        }
    }

    const unsigned FULL = 0xffffffffu;
    #pragma unroll
    for (int lvl = 0; lvl < 2; lvl++) {
        const int delta = 1 << lvl;
        const bool amLow = ((q & delta) == 0);
        float od0 = __shfl_xor_sync(FULL, bd0, delta);
        float od1 = __shfl_xor_sync(FULL, bd1, delta);
        float od2 = __shfl_xor_sync(FULL, bd2, delta);
        int   oi0 = __shfl_xor_sync(FULL, bi0, delta);
        int   oi1 = __shfl_xor_sync(FULL, bi1, delta);
        int   oi2 = __shfl_xor_sync(FULL, bi2, delta);

        float ld0 = amLow ? bd0 : od0, ld1 = amLow ? bd1 : od1, ld2 = amLow ? bd2 : od2;
        int   li0 = amLow ? bi0 : oi0, li1 = amLow ? bi1 : oi1, li2 = amLow ? bi2 : oi2;
        float hd0 = amLow ? od0 : bd0, hd1 = amLow ? od1 : bd1, hd2 = amLow ? od2 : bd2;
        int   hi0 = amLow ? oi0 : bi0, hi1 = amLow ? oi1 : bi1, hi2 = amLow ? oi2 : bi2;

        bool tA = ld0 <= hd0;
        float m0 = tA ? ld0 : hd0;  int x0 = tA ? li0 : hi0;
        float c1a = tA ? ld1 : ld0; int i1a = tA ? li1 : li0;
        float c1b = tA ? hd0 : hd1; int i1b = tA ? hi0 : hi1;
        bool tB = c1a <= c1b;
        float m1 = tB ? c1a : c1b;  int x1 = tB ? i1a : i1b;
        float c2a = tB ? (tA ? ld2 : ld1) : c1a;  int i2a = tB ? (tA ? li2 : li1) : i1a;
        float c2b = tB ? c1b : (tA ? hd1 : hd2);  int i2b = tB ? i1b : (tA ? hi1 : hi2);
        bool tC = c2a <= c2b;
        float m2 = tC ? c2a : c2b;  int x2 = tC ? i2a : i2b;

        bd0 = m0; bi0 = x0; bd1 = m1; bi1 = x1; bd2 = m2; bi2 = x2;
    }

    float w0 = 1.f / fmaxf(bd0, 1e-16f);
    float w1 = 1.f / fmaxf(bd1, 1e-16f);
    float w2 = 1.f / fmaxf(bd2, 1e-16f);
    const float inv = 1.f / (w0 + w1 + w2);
    w0 *= inv; w1 *= inv; w2 *= inv;

    const float4* r0 = (const float4*)(x + (size_t)(b * NC + bi0) * CC);
    const float4* r1 = (const float4*)(x + (size_t)(b * NC + bi1) * CC);
    const float4* r2 = (const float4*)(x + (size_t)(b * NC + bi2) * CC);
    const float4* xs = (const float4*)(x_skip + (size_t)f * CS);
    uint4* ga = (uint4*)(g_a1 + (size_t)f * CIN);

    for (int c8 = q; c8 < CIN / 8; c8 += 4) {
        float o[8];
        if (c8 < CC / 8) {
            float4 a0 = r0[2 * c8], a1 = r0[2 * c8 + 1];
            float4 b0 = r1[2 * c8], b1 = r1[2 * c8 + 1];
            float4 e0 = r2[2 * c8], e1 = r2[2 * c8 + 1];
            o[0] = w0*a0.x + w1*b0.x + w2*e0.x;  o[1] = w0*a0.y + w1*b0.y + w2*e0.y;
            o[2] = w0*a0.z + w1*b0.z + w2*e0.z;  o[3] = w0*a0.w + w1*b0.w + w2*e0.w;
            o[4] = w0*a1.x + w1*b1.x + w2*e1.x;  o[5] = w0*a1.y + w1*b1.y + w2*e1.y;
            o[6] = w0*a1.z + w1*b1.z + w2*e1.z;  o[7] = w0*a1.w + w1*b1.w + w2*e1.w;
        } else {
            int s8 = c8 - CC / 8;
            float4 s0 = xs[2 * s8], s1 = xs[2 * s8 + 1];
            o[0] = s0.x; o[1] = s0.y; o[2] = s0.z; o[3] = s0.w;
            o[4] = s1.x; o[5] = s1.y; o[6] = s1.z; o[7] = s1.w;
        }
        uint32_t hw[4];
        #pragma unroll
        for (int k = 0; k < 4; k++)
            hw[k] = pack_h2(__float2half_rn(o[2*k]), __float2half_rn(o[2*k+1]));
        ga[c8] = make_uint4(hw[0], hw[1], hw[2], hw[3]);
    }
}

// ---------------------------------------------------------------------------
// mma.sync fp16 GEMM, 2 MMA terms — round-11 config (128x128 tile, 256 thr,
// K64 double-buffered, 2 CTAs/SM) with the per-kstep MMA block split into two
// passes (all bh-term MMAs, then all bl-term MMAs) so dependent same-acc
// HMMAs are separated by 16 independent instructions.
// ---------------------------------------------------------------------------
#define TILEB    16384                 // 128 rows x 128B (64 fp16)
#define STAGEB   (3 * TILEB)           // A, Bh, Bl = 48 KB
#define GEMM_SMEM (2 * STAGEB)         // 96 KB

__global__ __launch_bounds__(256, 2) void gemm_mma_kernel(
    const __half* __restrict__ A,
    const __half* __restrict__ Bh, const __half* __restrict__ Bl,
    const float* __restrict__ bias, int K, int mode,
    __half* __restrict__ outA, float* __restrict__ outF,
    const float* __restrict__ gamma, const float* __restrict__ beta, int Nld)
{
    extern __shared__ char smem[];
    const uint32_t sbase = smem_u32(smem);
    const int tid = threadIdx.x;
    const int wid = tid >> 5, lid = tid & 31;
    const int warp_m = wid >> 2, warp_n = wid & 3;
    const int bm = blockIdx.y * 128, bn = blockIdx.x * 128;

    const int lr = tid >> 3;   // 0..31
    const int lu = tid & 7;    // 16B unit in 128B row
    const __half* gsrc[3] = {
        A  + (size_t)(bm + lr) * K + lu * 8,
        Bh + (size_t)(bn + lr) * K + lu * 8,
        Bl + (size_t)(bn + lr) * K + lu * 8 };

    const int nStages = K >> 6;

    auto load_stage = [&](int s) {
        const uint32_t dbase = sbase + (uint32_t)(s & 1) * STAGEB;
        const int k0 = s << 6;
        #pragma unroll
        for (int mtx = 0; mtx < 3; mtx++) {
            #pragma unroll
            for (int i = 0; i < 4; i++) {
                uint32_t byte = (uint32_t)(lr + i * 32) * 128 + lu * 16;
                cp16(dbase + mtx * TILEB + swz(byte),
                     gsrc[mtx] + (size_t)(i * 32) * K + k0);
            }
        }
        CP_COMMIT();
    };

    float acc[4][4][4];
    #pragma unroll
    for (int a = 0; a < 4; a++)
        #pragma unroll
        for (int b = 0; b < 4; b++)
            #pragma unroll
            for (int c = 0; c < 4; c++) acc[a][b][c] = 0.f;

    const int g  = lid >> 3;
    const int gr = lid & 7;
    const uint32_t aRow = warp_m * 64 + (g & 1) * 8 + gr;
    const uint32_t aCol = (uint32_t)(g >> 1) * 16;
    const uint32_t bRow = warp_n * 32 + (g >> 1) * 8 + gr;
    const uint32_t bCol = (uint32_t)(g & 1) * 16;

    load_stage(0);

    for (int s = 0; s < nStages; s++) {
        if (s + 1 < nStages) { load_stage(s + 1); CP_WAIT(1); }
        else                 { CP_WAIT(0); }
        __syncthreads();

        const uint32_t tb = sbase + (uint32_t)(s & 1) * STAGEB;
        #pragma unroll
        for (int kstep = 0; kstep < 4; kstep++) {
            const uint32_t kb = (uint32_t)kstep * 32;
            uint32_t ah[4][4], bh[4][2], bl[4][2];
            #pragma unroll
            for (int mf = 0; mf < 4; mf++) {
                uint32_t byte = (aRow + mf * 16) * 128 + aCol + kb;
                ldsm4(ah[mf], tb + swz(byte));
            }
            #pragma unroll
            for (int p = 0; p < 2; p++) {
                uint32_t byte = (bRow + p * 16) * 128 + bCol + kb;
                uint32_t rh[4], rl[4];
                ldsm4(rh, tb + TILEB + swz(byte));
                ldsm4(rl, tb + 2 * TILEB + swz(byte));
                bh[2*p][0] = rh[0]; bh[2*p][1] = rh[1];
                bh[2*p+1][0] = rh[2]; bh[2*p+1][1] = rh[3];
                bl[2*p][0] = rl[0]; bl[2*p][1] = rl[1];
                bl[2*p+1][0] = rl[2]; bl[2*p+1][1] = rl[3];
            }
            // pass 1: all hi-term MMAs (16 independent accumulators)
            #pragma unroll
            for (int mf = 0; mf < 4; mf++)
                #pragma unroll
                for (int nf = 0; nf < 4; nf++)
                    mma16816(acc[mf][nf], ah[mf], bh[nf]);
            // pass 2: all lo-term MMAs (dependent pairs now 16 apart)
            #pragma unroll
            for (int mf = 0; mf < 4; mf++)
                #pragma unroll
                for (int nf = 0; nf < 4; nf++)
                    mma16816(acc[mf][nf], ah[mf], bl[nf]);
        }
        __syncthreads();
    }

    // ---------------- epilogue ----------------
    #pragma unroll
    for (int mf = 0; mf < 4; mf++) {
        const int r0 = bm + warp_m * 64 + mf * 16 + (lid >> 2);
        const int r1 = r0 + 8;
        #pragma unroll
        for (int nf = 0; nf < 4; nf++) {
            const int c0 = bn + warp_n * 32 + nf * 8 + 2 * (lid & 3);
            const float bi0 = __ldg(bias + c0), bi1 = __ldg(bias + c0 + 1);
            float v00 = fmaxf(acc[mf][nf][0] + bi0, 0.f);
            float v01 = fmaxf(acc[mf][nf][1] + bi1, 0.f);
            float v10 = fmaxf(acc[mf][nf][2] + bi0, 0.f);
            float v11 = fmaxf(acc[mf][nf][3] + bi1, 0.f);

            if (mode == 0) {
                *(uint32_t*)(outA + (size_t)r0 * Nld + c0) =
                    pack_h2(__float2half_rn(v00), __float2half_rn(v01));
                *(uint32_t*)(outA + (size_t)r1 * Nld + c0) =
                    pack_h2(__float2half_rn(v10), __float2half_rn(v11));
            } else {
                float s1a = v00 + v01, s2a = v00 * v00 + v01 * v01;
                float s1b = v10 + v11, s2b = v10 * v10 + v11 * v11;
                s1a += __shfl_xor_sync(0xffffffffu, s1a, 1);
                s2a += __shfl_xor_sync(0xffffffffu, s2a, 1);
                s1b += __shfl_xor_sync(0xffffffffu, s1b, 1);
                s2b += __shfl_xor_sync(0xffffffffu, s2b, 1);
                s1a += __shfl_xor_sync(0xffffffffu, s1a, 2);
                s2a += __shfl_xor_sync(0xffffffffu, s2a, 2);
                s1b += __shfl_xor_sync(0xffffffffu, s1b, 2);
                s2b += __shfl_xor_sync(0xffffffffu, s2b, 2);
                const float mua = s1a * 0.125f, mub = s1b * 0.125f;
                const float isa = rsqrtf(s2a * 0.125f - mua * mua + GN_EPS);
                const float isb = rsqrtf(s2b * 0.125f - mub * mub + GN_EPS);
                const float g0 = __ldg(gamma + c0), g1 = __ldg(gamma + c0 + 1);
                const float t0 = __ldg(beta + c0),  t1 = __ldg(beta + c0 + 1);
                float2 oa = make_float2((v00 - mua) * isa * g0 + t0,
                                        (v01 - mua) * isa * g1 + t1);
                float2 ob = make_float2((v10 - mub) * isb * g0 + t0,
                                        (v11 - mub) * isb * g1 + t1);
                *(float2*)(outF + (size_t)r0 * Nld + c0) = oa;
                *(float2*)(outF + (size_t)r1 * Nld + c0) = ob;
            }
        }
    }
}

// ---------------------------------------------------------------------------
extern "C" void kernel_launch(void* const* d_in, const int* in_sizes, int n_in,
                              void* d_out, int out_size)
{
    const float* x         = (const float*)d_in[0];
    const float* pos       = (const float*)d_in[1];
    const float* x_skip    = (const float*)d_in[4];
    const float* pos_skip  = (const float*)d_in[5];
    const float* refl_skip = (const float*)d_in[6];
    const float* W1 = (const float*)d_in[8];
    const float* b1 = (const float*)d_in[9];
    const float* W2 = (const float*)d_in[10];
    const float* b2 = (const float*)d_in[11];
    const float* gamma = (const float*)d_in[12];
    const float* beta  = (const float*)d_in[13];
    float* out = (float*)d_out;

    __half *a1p, *h1p, *w1h, *w1l, *w2h, *w2l;
    cudaGetSymbolAddress((void**)&a1p, g_a1);
    cudaGetSymbolAddress((void**)&h1p, g_h1);
    cudaGetSymbolAddress((void**)&w1h, g_w1h);
    cudaGetSymbolAddress((void**)&w1l, g_w1l);
    cudaGetSymbolAddress((void**)&w2h, g_w2h);
    cudaGetSymbolAddress((void**)&w2l, g_w2l);

    static bool attr_done = false;
    if (!attr_done) {
        cudaFuncSetAttribute(gemm_mma_kernel,
                             cudaFuncAttributeMaxDynamicSharedMemorySize, GEMM_SMEM);
        attr_done = true;
    }

    const int n1 = H1W * CIN, n2 = H2W * H1W;
    split_kernel<<<(n1 + n2 + 255) / 256, 256>>>(W1, w1h, w1l, n1, W2, w2h, w2l, n2);

    // kNN + concat + folded tail passthroughs (round-11 structure)
    knn_interp_kernel<<<NBATCH * 128, 256>>>(x, pos, pos_skip, x_skip, refl_skip, out);

    // layer 1: h1 = relu(a1 @ W1^T + b1) -> fp16   [65536, 512]
    {
        dim3 grid(H1W / 128, MTOT / 128);
        gemm_mma_kernel<<<grid, 256, GEMM_SMEM>>>(
            a1p, w1h, w1l, b1, CIN, 0, h1p, nullptr, nullptr, nullptr, H1W);
    }
    // layer 2: out = GN(relu(h1 @ W2^T + b2))      [65536, 256]
    {
        dim3 grid(H2W / 128, MTOT / 128);
        gemm_mma_kernel<<<grid, 256, GEMM_SMEM>>>(
            h1p, w2h, w2l, b2, H1W, 1, nullptr, out, gamma, beta, H2W);
    }
}